// round 11
// baseline (speedup 1.0000x reference)
#include <cuda_runtime.h>

typedef unsigned long long u64;

#define HID 128
#define NA  1024
#define NR  1024

// Scratch: PA (bs1 folded in) and PR, row-major [row][h]
__device__ float g_PA[NA * HID];
__device__ float g_PR[NR * HID];

// ---------------- packed f32x2 helpers (sm_103a FADD2/FFMA2) ----------------
__device__ __forceinline__ u64 dup2(float v) {
    u64 d; asm("mov.b64 %0,{%1,%1};" : "=l"(d) : "f"(v)); return d;
}
__device__ __forceinline__ u64 pack2(float lo, float hi) {
    u64 d; asm("mov.b64 %0,{%1,%2};" : "=l"(d) : "f"(lo), "f"(hi)); return d;
}
__device__ __forceinline__ float2 unpack2(u64 d) {
    float2 r; asm("mov.b64 {%0,%1},%2;" : "=f"(r.x), "=f"(r.y) : "l"(d)); return r;
}
__device__ __forceinline__ u64 fadd2_(u64 a, u64 b) {
    u64 d; asm("add.rn.f32x2 %0,%1,%2;" : "=l"(d) : "l"(a), "l"(b)); return d;
}
__device__ __forceinline__ u64 ffma2_(u64 a, u64 b, u64 c) {
    u64 d; asm("fma.rn.f32x2 %0,%1,%2,%3;" : "=l"(d) : "l"(a), "l"(b), "l"(c)); return d;
}
__device__ __forceinline__ u64 relu2_(u64 x) {
    u64 d;
    asm("{\n\t.reg .f32 lo,hi;\n\t"
        "mov.b64 {lo,hi},%1;\n\t"
        "max.f32 lo,lo,0f00000000;\n\t"
        "max.f32 hi,hi,0f00000000;\n\t"
        "mov.b64 %0,{lo,hi};\n\t}"
        : "=l"(d) : "l"(x));
    return d;
}
// acc += relu(a2 + r2) * w, with wh = w/2 pre-halved:
//   relu(t)*w == (t + |t|) * (w/2)   (exact: power-of-2 scalings)
// |t| lanewise via and.b64 — NO pack/unpack movs, stays packed.
__device__ __forceinline__ u64 relufma2(u64 acc, u64 a2, u64 r2, u64 wh) {
    asm("{\n\t.reg .b64 t,ta;\n\t"
        "add.rn.f32x2 t,%1,%2;\n\t"
        "and.b64 ta,t,0x7FFFFFFF7FFFFFFF;\n\t"
        "add.rn.f32x2 t,t,ta;\n\t"
        "fma.rn.f32x2 %0,t,%3,%0;\n\t}"
        : "+l"(acc) : "l"(a2), "l"(r2), "l"(wh));
    return acc;
}

// ---------------------------------------------------------------------------
// 128x128 MLP layer pass, f32x2 row-pairs, 8-deep register prefetch of the
// weight column. hT is [k][row-pair] (broadcast reads, conflict-free).
// (round-4 proven embed path)
// ---------------------------------------------------------------------------
__device__ __forceinline__ void mlp128(const float* __restrict__ Wp, int j, int pb,
                                       const u64 (*__restrict__ hT)[8], u64 acc[4])
{
    acc[0] = acc[1] = acc[2] = acc[3] = 0ull;
    float wA[8], wB[8];
    #pragma unroll
    for (int i = 0; i < 8; ++i) wA[i] = Wp[i * HID + j];
    #pragma unroll 1
    for (int kb = 0; kb < 128; kb += 16) {
        #pragma unroll
        for (int i = 0; i < 8; ++i) wB[i] = Wp[(kb + 8 + i) * HID + j];
        #pragma unroll
        for (int i = 0; i < 8; ++i) {
            int k = kb + i;
            u64 w2 = dup2(wA[i]);
            ulonglong2 x01 = *(const ulonglong2*)&hT[k][pb];
            ulonglong2 x23 = *(const ulonglong2*)&hT[k][pb + 2];
            acc[0] = ffma2_(x01.x, w2, acc[0]);
            acc[1] = ffma2_(x01.y, w2, acc[1]);
            acc[2] = ffma2_(x23.x, w2, acc[2]);
            acc[3] = ffma2_(x23.y, w2, acc[3]);
        }
        #pragma unroll
        for (int i = 0; i < 8; ++i)
            wA[i] = (kb + 16 + i < 128) ? Wp[(kb + 16 + i) * HID + j] : 0.f;
        #pragma unroll
        for (int i = 0; i < 8; ++i) {
            int k = kb + 8 + i;
            u64 w2 = dup2(wB[i]);
            ulonglong2 x01 = *(const ulonglong2*)&hT[k][pb];
            ulonglong2 x23 = *(const ulonglong2*)&hT[k][pb + 2];
            acc[0] = ffma2_(x01.x, w2, acc[0]);
            acc[1] = ffma2_(x01.y, w2, acc[1]);
            acc[2] = ffma2_(x23.x, w2, acc[2]);
            acc[3] = ffma2_(x23.y, w2, acc[3]);
        }
    }
}

// ---------------------------------------------------------------------------
// Kernel 1: fused MLP chain. 128 blocks (64 agent + 64 region) x 256 threads,
// 16 rows per block. j = t&127 (column), half = t>>7 picks 4 of 8 row-pairs.
// (round-4 proven config)
// ---------------------------------------------------------------------------
__global__ __launch_bounds__(256) void embed_kernel(
    const float* __restrict__ xa,  const float* __restrict__ xr,
    const float* __restrict__ Wa1, const float* __restrict__ ba1,
    const float* __restrict__ Wa2, const float* __restrict__ ba2,
    const float* __restrict__ Wr1, const float* __restrict__ br1,
    const float* __restrict__ Wr2, const float* __restrict__ br2,
    const float* __restrict__ Ws1, const float* __restrict__ bs1)
{
    const int ROWS = 16;
    int blk = blockIdx.x;
    bool agent = blk < 64;
    int rbase = (agent ? blk : blk - 64) * ROWS;
    int idim = agent ? 24 : 20;
    const float* x  = agent ? (xa + rbase * 24) : (xr + rbase * 20);
    const float* W1 = agent ? Wa1 : Wr1;
    const float* b1 = agent ? ba1 : br1;
    const float* W2 = agent ? Wa2 : Wr2;
    const float* b2 = agent ? ba2 : br2;
    const float* Ws = agent ? Ws1 : (Ws1 + HID * HID);
    float* outp = agent ? g_PA : g_PR;

    __shared__ __align__(16) u64 xsp[24][8];   // packed input [k][row-pair]
    __shared__ __align__(16) u64 hT[HID][8];   // packed activ [k][row-pair]

    int t = threadIdx.x;
    int j = t & 127;
    int pb = (t >> 7) * 4;     // row-pair base (0 or 4)

    // Stage packed input rows
    for (int i = t; i < idim * 8; i += 256) {
        int k = i >> 3, p = i & 7;
        xsp[k][p] = pack2(x[(2 * p) * idim + k], x[(2 * p + 1) * idim + k]);
    }
    __syncthreads();

    // Layer 1
    u64 acc[4];
    {
        u64 bp = dup2(b1[j]);
        acc[0] = acc[1] = acc[2] = acc[3] = bp;
        #pragma unroll 4
        for (int k = 0; k < idim; ++k) {
            u64 w2 = dup2(W1[k * HID + j]);
            ulonglong2 x01 = *(const ulonglong2*)&xsp[k][pb];
            ulonglong2 x23 = *(const ulonglong2*)&xsp[k][pb + 2];
            acc[0] = ffma2_(x01.x, w2, acc[0]);
            acc[1] = ffma2_(x01.y, w2, acc[1]);
            acc[2] = ffma2_(x23.x, w2, acc[2]);
            acc[3] = ffma2_(x23.y, w2, acc[3]);
        }
        #pragma unroll
        for (int p = 0; p < 4; ++p) hT[j][pb + p] = relu2_(acc[p]);
    }
    __syncthreads();

    // Layer 2
    mlp128(W2, j, pb, hT, acc);
    {
        u64 b2d = dup2(b2[j]);
        __syncthreads();             // all hT reads done before overwrite
        #pragma unroll
        for (int p = 0; p < 4; ++p)
            hT[j][pb + p] = relu2_(fadd2_(acc[p], b2d));
    }
    __syncthreads();

    // Score projection
    mlp128(Ws, j, pb, hT, acc);
    u64 bsd = agent ? dup2(bs1[j]) : 0ull;
    #pragma unroll
    for (int p = 0; p < 4; ++p) {
        u64 v = agent ? fadd2_(acc[p], bsd) : acc[p];
        float2 f = unpack2(v);
        int row = rbase + 2 * (pb + p);
        outp[row * HID + j]       = f.x;
        outp[(row + 1) * HID + j] = f.y;
    }
}

// ---------------------------------------------------------------------------
// Kernel 2: pairwise scores, f32x2 packed over (h, h+1), mov-free relu.
// Block tile 64a x 32r, 128 threads, 4a x 4r register tile per thread
// (a = ty+16i, r = tx+8jj). Weights staged PRE-HALVED so
// acc += (t+|t|)*(w/2) == relu(t)*w exactly. Pitch 68. Grid 512.
// ---------------------------------------------------------------------------
__global__ __launch_bounds__(128, 6) void pair_kernel(
    const float* __restrict__ Ws2, const float* __restrict__ bs2,
    float* __restrict__ out)
{
    __shared__ __align__(16) float As[64 * 68];   // [a][h_local], 17.4KB
    __shared__ __align__(16) float Rs[32 * 68];   // [r][h_local],  8.7KB
    __shared__ __align__(16) u64   wsp[64];       // Ws2/2 as natural h-pairs

    int t  = threadIdx.x;
    int tx = t & 7;          // r = tx + 8*jj
    int ty = t >> 3;         // a = ty + 16*i   (ty 0..15)
    int a0 = blockIdx.y * 64;
    int r0 = blockIdx.x * 32;

    if (t < 64) {            // stage pre-halved weight pairs
        float2 w = ((const float2*)Ws2)[t];
        wsp[t] = pack2(w.x * 0.5f, w.y * 0.5f);
    }

    u64 acc[4][4];
    #pragma unroll
    for (int i = 0; i < 4; ++i)
        #pragma unroll
        for (int jj = 0; jj < 4; ++jj) acc[i][jj] = 0ull;

    const u64* As64 = (const u64*)As;   // pitch 34 u64
    const u64* Rs64 = (const u64*)Rs;

    for (int c = 0; c < 2; ++c) {
        int hb = 64 * c;
        __syncthreads();   // previous chunk's reads done (and wsp on c==0)

        #pragma unroll
        for (int it = 0; it < 8; ++it) {
            int idx = t + 128 * it;
            int row = idx >> 4, c4 = idx & 15;
            *(float4*)&As[row * 68 + 4 * c4] =
                *(const float4*)&g_PA[(size_t)(a0 + row) * HID + hb + 4 * c4];
        }
        #pragma unroll
        for (int it = 0; it < 4; ++it) {
            int idx = t + 128 * it;
            int row = idx >> 4, c4 = idx & 15;
            *(float4*)&Rs[row * 68 + 4 * c4] =
                *(const float4*)&g_PR[(size_t)(r0 + row) * HID + hb + 4 * c4];
        }
        __syncthreads();

        #pragma unroll 2
        for (int hd = 0; hd < 16; ++hd) {   // 2 packed h-pairs per iter
            int hp = 2 * hd;
            ulonglong2 wv = *(const ulonglong2*)&wsp[32 * c + hp];
            ulonglong2 av[4], rv[4];
            #pragma unroll
            for (int i = 0; i < 4; ++i)
                av[i] = *(const ulonglong2*)&As64[(ty + 16 * i) * 34 + hp];
            #pragma unroll
            for (int jj = 0; jj < 4; ++jj)
                rv[jj] = *(const ulonglong2*)&Rs64[(tx + 8 * jj) * 34 + hp];
            #pragma unroll
            for (int i = 0; i < 4; ++i)
                #pragma unroll
                for (int jj = 0; jj < 4; ++jj) {
                    acc[i][jj] = relufma2(acc[i][jj], av[i].x, rv[jj].x, wv.x);
                    acc[i][jj] = relufma2(acc[i][jj], av[i].y, rv[jj].y, wv.y);
                }
        }
    }

    float b = *bs2;
    #pragma unroll
    for (int i = 0; i < 4; ++i) {
        int a = a0 + ty + 16 * i;
        #pragma unroll
        for (int jj = 0; jj < 4; ++jj) {
            float2 p = unpack2(acc[i][jj]);
            out[(size_t)a * NR + r0 + tx + 8 * jj] = (p.x + p.y) + b;
        }
    }
}

// ---------------------------------------------------------------------------
extern "C" void kernel_launch(void* const* d_in, const int* in_sizes, int n_in,
                              void* d_out, int out_size)
{
    const float* xa  = (const float*)d_in[0];
    const float* xr  = (const float*)d_in[1];
    const float* Wa1 = (const float*)d_in[2];
    const float* ba1 = (const float*)d_in[3];
    const float* Wa2 = (const float*)d_in[4];
    const float* ba2 = (const float*)d_in[5];
    const float* Wr1 = (const float*)d_in[6];
    const float* br1 = (const float*)d_in[7];
    const float* Wr2 = (const float*)d_in[8];
    const float* br2 = (const float*)d_in[9];
    const float* Ws1 = (const float*)d_in[10];
    const float* bs1 = (const float*)d_in[11];
    const float* Ws2 = (const float*)d_in[12];
    const float* bs2 = (const float*)d_in[13];
    float* out = (float*)d_out;

    embed_kernel<<<128, 256>>>(xa, xr, Wa1, ba1, Wa2, ba2,
                               Wr1, br1, Wr2, br2, Ws1, bs1);
    pair_kernel<<<dim3(NR / 32, NA / 64), 128>>>(Ws2, bs2, out);
}

// round 12
// speedup vs baseline: 1.1404x; 1.1404x over previous
#include <cuda_runtime.h>

typedef unsigned long long u64;

#define HID 128
#define NA  1024
#define NR  1024

// Scratch: PA (bs1 folded in) and PR, row-major [row][h]
__device__ float g_PA[NA * HID];
__device__ float g_PR[NR * HID];

// ---------------- packed f32x2 helpers (sm_103a FADD2/FFMA2) ----------------
__device__ __forceinline__ u64 dup2(float v) {
    u64 d; asm("mov.b64 %0,{%1,%1};" : "=l"(d) : "f"(v)); return d;
}
__device__ __forceinline__ u64 pack2(float lo, float hi) {
    u64 d; asm("mov.b64 %0,{%1,%2};" : "=l"(d) : "f"(lo), "f"(hi)); return d;
}
__device__ __forceinline__ float2 unpack2(u64 d) {
    float2 r; asm("mov.b64 {%0,%1},%2;" : "=f"(r.x), "=f"(r.y) : "l"(d)); return r;
}
__device__ __forceinline__ u64 fadd2_(u64 a, u64 b) {
    u64 d; asm("add.rn.f32x2 %0,%1,%2;" : "=l"(d) : "l"(a), "l"(b)); return d;
}
__device__ __forceinline__ u64 ffma2_(u64 a, u64 b, u64 c) {
    u64 d; asm("fma.rn.f32x2 %0,%1,%2,%3;" : "=l"(d) : "l"(a), "l"(b), "l"(c)); return d;
}
__device__ __forceinline__ u64 relu2_(u64 x) {
    u64 d;
    asm("{\n\t.reg .f32 lo,hi;\n\t"
        "mov.b64 {lo,hi},%1;\n\t"
        "max.f32 lo,lo,0f00000000;\n\t"
        "max.f32 hi,hi,0f00000000;\n\t"
        "mov.b64 %0,{lo,hi};\n\t}"
        : "=l"(d) : "l"(x));
    return d;
}
// acc += relu(a2 + r2) * w2  (2 h-lanes packed; ptxas fuses the scalar maxes
// into a packed FMNMX on the alu pipe -> 2 fma-pipe + 1 alu-pipe ops)
__device__ __forceinline__ u64 addrelufma(u64 acc, u64 a2, u64 r2, u64 w2) {
    asm("{\n\t.reg .b64 t;\n\t.reg .f32 lo,hi;\n\t"
        "add.rn.f32x2 t,%1,%2;\n\t"
        "mov.b64 {lo,hi},t;\n\t"
        "max.f32 lo,lo,0f00000000;\n\t"
        "max.f32 hi,hi,0f00000000;\n\t"
        "mov.b64 t,{lo,hi};\n\t"
        "fma.rn.f32x2 %0,t,%3,%0;\n\t}"
        : "+l"(acc) : "l"(a2), "l"(r2), "l"(w2));
    return acc;
}

// ---------------------------------------------------------------------------
// Kernel 1: fused MLP chain. 512 blocks (256 agent + 256 region) x 128
// threads, 4 rows per block. Thread t = output column; owns 2 row-pairs.
// Each of the 4 warps covers a DISTINCT 32-column slice -> no intra-block
// LDG redundancy; 3.46 blocks/SM -> 3.46 warps/SMSP hides LDG latency.
// ---------------------------------------------------------------------------
__device__ __forceinline__ void mlp4(const float* __restrict__ Wp, int j,
                                     const u64 (*__restrict__ hT)[2], u64 acc[2])
{
    acc[0] = acc[1] = 0ull;
    float wA[8], wB[8];
    #pragma unroll
    for (int i = 0; i < 8; ++i) wA[i] = Wp[i * HID + j];
    #pragma unroll 1
    for (int kb = 0; kb < 128; kb += 16) {
        #pragma unroll
        for (int i = 0; i < 8; ++i) wB[i] = Wp[(kb + 8 + i) * HID + j];
        #pragma unroll
        for (int i = 0; i < 8; ++i) {
            u64 w2 = dup2(wA[i]);
            ulonglong2 x01 = *(const ulonglong2*)&hT[kb + i][0];
            acc[0] = ffma2_(x01.x, w2, acc[0]);
            acc[1] = ffma2_(x01.y, w2, acc[1]);
        }
        #pragma unroll
        for (int i = 0; i < 8; ++i)
            wA[i] = (kb + 16 + i < 128) ? Wp[(kb + 16 + i) * HID + j] : 0.f;
        #pragma unroll
        for (int i = 0; i < 8; ++i) {
            u64 w2 = dup2(wB[i]);
            ulonglong2 x01 = *(const ulonglong2*)&hT[kb + 8 + i][0];
            acc[0] = ffma2_(x01.x, w2, acc[0]);
            acc[1] = ffma2_(x01.y, w2, acc[1]);
        }
    }
}

__global__ __launch_bounds__(128) void embed_kernel(
    const float* __restrict__ xa,  const float* __restrict__ xr,
    const float* __restrict__ Wa1, const float* __restrict__ ba1,
    const float* __restrict__ Wa2, const float* __restrict__ ba2,
    const float* __restrict__ Wr1, const float* __restrict__ br1,
    const float* __restrict__ Wr2, const float* __restrict__ br2,
    const float* __restrict__ Ws1, const float* __restrict__ bs1)
{
    const int ROWS = 4;
    int blk = blockIdx.x;
    bool agent = blk < 256;
    int rbase = (agent ? blk : blk - 256) * ROWS;
    int idim = agent ? 24 : 20;
    const float* x  = agent ? (xa + rbase * 24) : (xr + rbase * 20);
    const float* W1 = agent ? Wa1 : Wr1;
    const float* b1 = agent ? ba1 : br1;
    const float* W2 = agent ? Wa2 : Wr2;
    const float* b2 = agent ? ba2 : br2;
    const float* Ws = agent ? Ws1 : (Ws1 + HID * HID);
    float* outp = agent ? g_PA : g_PR;

    __shared__ __align__(16) u64 xp[24][2];   // packed input [k][row-pair]
    __shared__ __align__(16) u64 hT[HID][2];  // packed activ [k][row-pair]

    int j = threadIdx.x;   // output column

    // Stage packed input rows (2 row-pairs)
    if (j < idim * 2) {
        int k = j >> 1, p = j & 1;
        xp[k][p] = pack2(x[(2 * p) * idim + k], x[(2 * p + 1) * idim + k]);
    }
    __syncthreads();

    // Layer 1
    u64 acc[2];
    {
        u64 bp = dup2(b1[j]);
        acc[0] = acc[1] = bp;
        #pragma unroll 4
        for (int k = 0; k < idim; ++k) {
            u64 w2 = dup2(W1[k * HID + j]);
            ulonglong2 x01 = *(const ulonglong2*)&xp[k][0];
            acc[0] = ffma2_(x01.x, w2, acc[0]);
            acc[1] = ffma2_(x01.y, w2, acc[1]);
        }
        hT[j][0] = relu2_(acc[0]);
        hT[j][1] = relu2_(acc[1]);
    }
    __syncthreads();

    // Layer 2
    mlp4(W2, j, hT, acc);
    {
        u64 b2d = dup2(b2[j]);
        __syncthreads();             // all hT reads done before overwrite
        hT[j][0] = relu2_(fadd2_(acc[0], b2d));
        hT[j][1] = relu2_(fadd2_(acc[1], b2d));
    }
    __syncthreads();

    // Score projection
    mlp4(Ws, j, hT, acc);
    u64 bsd = agent ? dup2(bs1[j]) : 0ull;
    #pragma unroll
    for (int p = 0; p < 2; ++p) {
        u64 v = agent ? fadd2_(acc[p], bsd) : acc[p];
        float2 f = unpack2(v);
        int row = rbase + 2 * p;
        outp[row * HID + j]       = f.x;
        outp[(row + 1) * HID + j] = f.y;
    }
}

// ---------------------------------------------------------------------------
// Kernel 2: pairwise scores, f32x2 packed over (h, h+1).  (round-7 proven)
// Block tile 64a x 32r, 128 threads, 4a x 4r register tile per thread
// (a = ty+16i, r = tx+8jj). Two h-pairs fetched per LDS.128.
// Pitch 68 floats (16B-aligned rows; conflict-free). Grid 512.
// ---------------------------------------------------------------------------
__global__ __launch_bounds__(128, 6) void pair_kernel(
    const float* __restrict__ Ws2, const float* __restrict__ bs2,
    float* __restrict__ out)
{
    __shared__ __align__(16) float As[64 * 68];   // [a][h_local], 17.4KB
    __shared__ __align__(16) float Rs[32 * 68];   // [r][h_local],  8.7KB
    __shared__ __align__(16) u64   wsp[64];       // Ws2 as natural h-pairs

    int t  = threadIdx.x;
    int tx = t & 7;          // r = tx + 8*jj
    int ty = t >> 3;         // a = ty + 16*i   (ty 0..15)
    int a0 = blockIdx.y * 64;
    int r0 = blockIdx.x * 32;

    if (t < 64) wsp[t] = ((const u64*)Ws2)[t];

    u64 acc[4][4];
    #pragma unroll
    for (int i = 0; i < 4; ++i)
        #pragma unroll
        for (int jj = 0; jj < 4; ++jj) acc[i][jj] = 0ull;

    const u64* As64 = (const u64*)As;   // pitch 34 u64
    const u64* Rs64 = (const u64*)Rs;

    for (int c = 0; c < 2; ++c) {
        int hb = 64 * c;
        __syncthreads();   // previous chunk's reads done (and wsp on c==0)

        #pragma unroll
        for (int it = 0; it < 8; ++it) {
            int idx = t + 128 * it;
            int row = idx >> 4, c4 = idx & 15;
            *(float4*)&As[row * 68 + 4 * c4] =
                *(const float4*)&g_PA[(size_t)(a0 + row) * HID + hb + 4 * c4];
        }
        #pragma unroll
        for (int it = 0; it < 4; ++it) {
            int idx = t + 128 * it;
            int row = idx >> 4, c4 = idx & 15;
            *(float4*)&Rs[row * 68 + 4 * c4] =
                *(const float4*)&g_PR[(size_t)(r0 + row) * HID + hb + 4 * c4];
        }
        __syncthreads();

        #pragma unroll 2
        for (int hd = 0; hd < 16; ++hd) {   // 2 packed h-pairs per iter
            int hp = 2 * hd;
            ulonglong2 wv = *(const ulonglong2*)&wsp[32 * c + hp];
            ulonglong2 av[4], rv[4];
            #pragma unroll
            for (int i = 0; i < 4; ++i)
                av[i] = *(const ulonglong2*)&As64[(ty + 16 * i) * 34 + hp];
            #pragma unroll
            for (int jj = 0; jj < 4; ++jj)
                rv[jj] = *(const ulonglong2*)&Rs64[(tx + 8 * jj) * 34 + hp];
            #pragma unroll
            for (int i = 0; i < 4; ++i)
                #pragma unroll
                for (int jj = 0; jj < 4; ++jj) {
                    acc[i][jj] = addrelufma(acc[i][jj], av[i].x, rv[jj].x, wv.x);
                    acc[i][jj] = addrelufma(acc[i][jj], av[i].y, rv[jj].y, wv.y);
                }
        }
    }

    float b = *bs2;
    #pragma unroll
    for (int i = 0; i < 4; ++i) {
        int a = a0 + ty + 16 * i;
        #pragma unroll
        for (int jj = 0; jj < 4; ++jj) {
            float2 p = unpack2(acc[i][jj]);
            out[(size_t)a * NR + r0 + tx + 8 * jj] = (p.x + p.y) + b;
        }
    }
}

// ---------------------------------------------------------------------------
extern "C" void kernel_launch(void* const* d_in, const int* in_sizes, int n_in,
                              void* d_out, int out_size)
{
    const float* xa  = (const float*)d_in[0];
    const float* xr  = (const float*)d_in[1];
    const float* Wa1 = (const float*)d_in[2];
    const float* ba1 = (const float*)d_in[3];
    const float* Wa2 = (const float*)d_in[4];
    const float* ba2 = (const float*)d_in[5];
    const float* Wr1 = (const float*)d_in[6];
    const float* br1 = (const float*)d_in[7];
    const float* Wr2 = (const float*)d_in[8];
    const float* br2 = (const float*)d_in[9];
    const float* Ws1 = (const float*)d_in[10];
    const float* bs1 = (const float*)d_in[11];
    const float* Ws2 = (const float*)d_in[12];
    const float* bs2 = (const float*)d_in[13];
    float* out = (float*)d_out;

    embed_kernel<<<512, 128>>>(xa, xr, Wa1, ba1, Wa2, ba2,
                               Wr1, br1, Wr2, br2, Ws1, bs1);
    pair_kernel<<<dim3(NR / 32, NA / 64), 128>>>(Ws2, bs2, out);
}

// round 13
// speedup vs baseline: 1.1491x; 1.0077x over previous
#include <cuda_runtime.h>

typedef unsigned long long u64;

#define HID 128
#define NA  1024
#define NR  1024

// Scratch: PA (bs1 folded in) and PR, row-major [row][h]
__device__ float g_PA[NA * HID];
__device__ float g_PR[NR * HID];

// ---------------- packed f32x2 helpers (sm_103a FADD2/FFMA2) ----------------
__device__ __forceinline__ u64 dup2(float v) {
    u64 d; asm("mov.b64 %0,{%1,%1};" : "=l"(d) : "f"(v)); return d;
}
__device__ __forceinline__ u64 pack2(float lo, float hi) {
    u64 d; asm("mov.b64 %0,{%1,%2};" : "=l"(d) : "f"(lo), "f"(hi)); return d;
}
__device__ __forceinline__ float2 unpack2(u64 d) {
    float2 r; asm("mov.b64 {%0,%1},%2;" : "=f"(r.x), "=f"(r.y) : "l"(d)); return r;
}
__device__ __forceinline__ u64 fadd2_(u64 a, u64 b) {
    u64 d; asm("add.rn.f32x2 %0,%1,%2;" : "=l"(d) : "l"(a), "l"(b)); return d;
}
__device__ __forceinline__ u64 ffma2_(u64 a, u64 b, u64 c) {
    u64 d; asm("fma.rn.f32x2 %0,%1,%2,%3;" : "=l"(d) : "l"(a), "l"(b), "l"(c)); return d;
}
__device__ __forceinline__ u64 relu2_(u64 x) {
    u64 d;
    asm("{\n\t.reg .f32 lo,hi;\n\t"
        "mov.b64 {lo,hi},%1;\n\t"
        "max.f32 lo,lo,0f00000000;\n\t"
        "max.f32 hi,hi,0f00000000;\n\t"
        "mov.b64 %0,{lo,hi};\n\t}"
        : "=l"(d) : "l"(x));
    return d;
}
// acc += relu(a2 + r2) * w2  (2 h-lanes packed; compiles to
// FADD2 + 2 scalar FMNMX (pair-aliased regs, no movs) + FFMA2)
__device__ __forceinline__ u64 addrelufma(u64 acc, u64 a2, u64 r2, u64 w2) {
    asm("{\n\t.reg .b64 t;\n\t.reg .f32 lo,hi;\n\t"
        "add.rn.f32x2 t,%1,%2;\n\t"
        "mov.b64 {lo,hi},t;\n\t"
        "max.f32 lo,lo,0f00000000;\n\t"
        "max.f32 hi,hi,0f00000000;\n\t"
        "mov.b64 t,{lo,hi};\n\t"
        "fma.rn.f32x2 %0,t,%3,%0;\n\t}"
        : "+l"(acc) : "l"(a2), "l"(r2), "l"(w2));
    return acc;
}

// ---------------------------------------------------------------------------
// 128x128 MLP layer pass over 2 row-pairs (one quarter's share), 8-deep
// register prefetch of the weight column. hT reads are full-warp broadcasts.
// ---------------------------------------------------------------------------
__device__ __forceinline__ void mlp128_q(const float* __restrict__ Wp, int j, int pb,
                                         const u64 (*__restrict__ hT)[8], u64 acc[2])
{
    acc[0] = acc[1] = 0ull;
    float wA[8], wB[8];
    #pragma unroll
    for (int i = 0; i < 8; ++i) wA[i] = Wp[i * HID + j];
    #pragma unroll 1
    for (int kb = 0; kb < 128; kb += 16) {
        #pragma unroll
        for (int i = 0; i < 8; ++i) wB[i] = Wp[(kb + 8 + i) * HID + j];
        #pragma unroll
        for (int i = 0; i < 8; ++i) {
            u64 w2 = dup2(wA[i]);
            ulonglong2 x01 = *(const ulonglong2*)&hT[kb + i][pb];
            acc[0] = ffma2_(x01.x, w2, acc[0]);
            acc[1] = ffma2_(x01.y, w2, acc[1]);
        }
        #pragma unroll
        for (int i = 0; i < 8; ++i)
            wA[i] = (kb + 16 + i < 128) ? Wp[(kb + 16 + i) * HID + j] : 0.f;
        #pragma unroll
        for (int i = 0; i < 8; ++i) {
            u64 w2 = dup2(wB[i]);
            ulonglong2 x01 = *(const ulonglong2*)&hT[kb + 8 + i][pb];
            acc[0] = ffma2_(x01.x, w2, acc[0]);
            acc[1] = ffma2_(x01.y, w2, acc[1]);
        }
    }
}

// ---------------------------------------------------------------------------
// Kernel 1: fused MLP chain. 128 blocks (64 agent + 64 region) x 512 threads,
// 16 rows per block. j = t&127 (output column); quarter = t>>7 owns 2 of the
// 8 row-pairs. Minimal weight traffic (128 blocks) AND 4 warps/SMSP.
// ---------------------------------------------------------------------------
__global__ __launch_bounds__(512) void embed_kernel(
    const float* __restrict__ xa,  const float* __restrict__ xr,
    const float* __restrict__ Wa1, const float* __restrict__ ba1,
    const float* __restrict__ Wa2, const float* __restrict__ ba2,
    const float* __restrict__ Wr1, const float* __restrict__ br1,
    const float* __restrict__ Wr2, const float* __restrict__ br2,
    const float* __restrict__ Ws1, const float* __restrict__ bs1)
{
    const int ROWS = 16;
    int blk = blockIdx.x;
    bool agent = blk < 64;
    int rbase = (agent ? blk : blk - 64) * ROWS;
    int idim = agent ? 24 : 20;
    const float* x  = agent ? (xa + rbase * 24) : (xr + rbase * 20);
    const float* W1 = agent ? Wa1 : Wr1;
    const float* b1 = agent ? ba1 : br1;
    const float* W2 = agent ? Wa2 : Wr2;
    const float* b2 = agent ? ba2 : br2;
    const float* Ws = agent ? Ws1 : (Ws1 + HID * HID);
    float* outp = agent ? g_PA : g_PR;

    __shared__ __align__(16) u64 xsp[24][8];   // packed input [k][row-pair]
    __shared__ __align__(16) u64 hT[HID][8];   // packed activ [k][row-pair]

    int t  = threadIdx.x;
    int j  = t & 127;
    int pb = (t >> 7) * 2;     // row-pair base (0,2,4,6)

    // Stage packed input rows
    if (t < idim * 8) {
        int k = t >> 3, p = t & 7;
        xsp[k][p] = pack2(x[(2 * p) * idim + k], x[(2 * p + 1) * idim + k]);
    }
    __syncthreads();

    // Layer 1 (each thread: its 2 row-pairs only)
    u64 acc[2];
    {
        u64 bp = dup2(b1[j]);
        acc[0] = acc[1] = bp;
        #pragma unroll 4
        for (int k = 0; k < idim; ++k) {
            u64 w2 = dup2(W1[k * HID + j]);
            ulonglong2 x01 = *(const ulonglong2*)&xsp[k][pb];
            acc[0] = ffma2_(x01.x, w2, acc[0]);
            acc[1] = ffma2_(x01.y, w2, acc[1]);
        }
        hT[j][pb]     = relu2_(acc[0]);
        hT[j][pb + 1] = relu2_(acc[1]);
    }
    __syncthreads();

    // Layer 2
    mlp128_q(W2, j, pb, hT, acc);
    {
        u64 b2d = dup2(b2[j]);
        __syncthreads();             // all hT reads done before overwrite
        hT[j][pb]     = relu2_(fadd2_(acc[0], b2d));
        hT[j][pb + 1] = relu2_(fadd2_(acc[1], b2d));
    }
    __syncthreads();

    // Score projection
    mlp128_q(Ws, j, pb, hT, acc);
    u64 bsd = agent ? dup2(bs1[j]) : 0ull;
    #pragma unroll
    for (int p = 0; p < 2; ++p) {
        u64 v = agent ? fadd2_(acc[p], bsd) : acc[p];
        float2 f = unpack2(v);
        int row = rbase + 2 * (pb + p);
        outp[row * HID + j]       = f.x;
        outp[(row + 1) * HID + j] = f.y;
    }
}

// ---------------------------------------------------------------------------
// Kernel 2: pairwise scores, f32x2 packed over (h, h+1).  (round-7 proven)
// Block tile 64a x 32r, 128 threads, 4a x 4r register tile per thread
// (a = ty+16i, r = tx+8jj). Two h-pairs fetched per LDS.128.
// Pitch 68 floats (16B-aligned rows; conflict-free). Grid 512.
// ---------------------------------------------------------------------------
__global__ __launch_bounds__(128, 6) void pair_kernel(
    const float* __restrict__ Ws2, const float* __restrict__ bs2,
    float* __restrict__ out)
{
    __shared__ __align__(16) float As[64 * 68];   // [a][h_local], 17.4KB
    __shared__ __align__(16) float Rs[32 * 68];   // [r][h_local],  8.7KB
    __shared__ __align__(16) u64   wsp[64];       // Ws2 as natural h-pairs

    int t  = threadIdx.x;
    int tx = t & 7;          // r = tx + 8*jj
    int ty = t >> 3;         // a = ty + 16*i   (ty 0..15)
    int a0 = blockIdx.y * 64;
    int r0 = blockIdx.x * 32;

    if (t < 64) wsp[t] = ((const u64*)Ws2)[t];

    u64 acc[4][4];
    #pragma unroll
    for (int i = 0; i < 4; ++i)
        #pragma unroll
        for (int jj = 0; jj < 4; ++jj) acc[i][jj] = 0ull;

    const u64* As64 = (const u64*)As;   // pitch 34 u64
    const u64* Rs64 = (const u64*)Rs;

    for (int c = 0; c < 2; ++c) {
        int hb = 64 * c;
        __syncthreads();   // previous chunk's reads done (and wsp on c==0)

        #pragma unroll
        for (int it = 0; it < 8; ++it) {
            int idx = t + 128 * it;
            int row = idx >> 4, c4 = idx & 15;
            *(float4*)&As[row * 68 + 4 * c4] =
                *(const float4*)&g_PA[(size_t)(a0 + row) * HID + hb + 4 * c4];
        }
        #pragma unroll
        for (int it = 0; it < 4; ++it) {
            int idx = t + 128 * it;
            int row = idx >> 4, c4 = idx & 15;
            *(float4*)&Rs[row * 68 + 4 * c4] =
                *(const float4*)&g_PR[(size_t)(r0 + row) * HID + hb + 4 * c4];
        }
        __syncthreads();

        #pragma unroll 2
        for (int hd = 0; hd < 16; ++hd) {   // 2 packed h-pairs per iter
            int hp = 2 * hd;
            ulonglong2 wv = *(const ulonglong2*)&wsp[32 * c + hp];
            ulonglong2 av[4], rv[4];
            #pragma unroll
            for (int i = 0; i < 4; ++i)
                av[i] = *(const ulonglong2*)&As64[(ty + 16 * i) * 34 + hp];
            #pragma unroll
            for (int jj = 0; jj < 4; ++jj)
                rv[jj] = *(const ulonglong2*)&Rs64[(tx + 8 * jj) * 34 + hp];
            #pragma unroll
            for (int i = 0; i < 4; ++i)
                #pragma unroll
                for (int jj = 0; jj < 4; ++jj) {
                    acc[i][jj] = addrelufma(acc[i][jj], av[i].x, rv[jj].x, wv.x);
                    acc[i][jj] = addrelufma(acc[i][jj], av[i].y, rv[jj].y, wv.y);
                }
        }
    }

    float b = *bs2;
    #pragma unroll
    for (int i = 0; i < 4; ++i) {
        int a = a0 + ty + 16 * i;
        #pragma unroll
        for (int jj = 0; jj < 4; ++jj) {
            float2 p = unpack2(acc[i][jj]);
            out[(size_t)a * NR + r0 + tx + 8 * jj] = (p.x + p.y) + b;
        }
    }
}

// ---------------------------------------------------------------------------
extern "C" void kernel_launch(void* const* d_in, const int* in_sizes, int n_in,
                              void* d_out, int out_size)
{
    const float* xa  = (const float*)d_in[0];
    const float* xr  = (const float*)d_in[1];
    const float* Wa1 = (const float*)d_in[2];
    const float* ba1 = (const float*)d_in[3];
    const float* Wa2 = (const float*)d_in[4];
    const float* ba2 = (const float*)d_in[5];
    const float* Wr1 = (const float*)d_in[6];
    const float* br1 = (const float*)d_in[7];
    const float* Wr2 = (const float*)d_in[8];
    const float* br2 = (const float*)d_in[9];
    const float* Ws1 = (const float*)d_in[10];
    const float* bs1 = (const float*)d_in[11];
    const float* Ws2 = (const float*)d_in[12];
    const float* bs2 = (const float*)d_in[13];
    float* out = (float*)d_out;

    embed_kernel<<<128, 512>>>(xa, xr, Wa1, ba1, Wa2, ba2,
                               Wr1, br1, Wr2, br2, Ws1, bs1);
    pair_kernel<<<dim3(NR / 32, NA / 64), 128>>>(Ws2, bs2, out);
}